// round 16
// baseline (speedup 1.0000x reference)
#include <cuda_runtime.h>
#include <cstdint>

// ---------------------------------------------------------------------------
// SparseMoE: T=4096 tokens, H=2048, I=8192, E=8, top_k=2
// Round 7: occupancy fix. 128-thread CTAs (4 warps, 128x128 block tile,
// 64x64 warp tiles), 3-stage cp.async pipeline, 106KB smem -> 2 CTAs/SM.
// Two co-resident CTAs hide each other's barrier/pipeline stalls.
// ---------------------------------------------------------------------------

#define T_TOK 4096
#define HDIM  2048
#define IDIM  8192
#define NEXP  8
#define SLOTS 8192

__device__ float g_hmid[(size_t)SLOTS * IDIM];   // 256 MB
__device__ float g_y[(size_t)SLOTS * HDIM];      // 64 MB
__device__ int   g_tok[SLOTS];
__device__ int   g_slot_for[T_TOK * 2];
__device__ float g_wts[T_TOK * 2];
__device__ int   g_sel[T_TOK * 2];
__device__ int   g_cnt[NEXP];
__device__ int   g_basearr[NEXP];

// ---------------------------------------------------------------------------
// helpers
// ---------------------------------------------------------------------------
__device__ __forceinline__ uint32_t smem_u32(const void* p) {
    uint32_t a;
    asm("{ .reg .u64 t; cvta.to.shared.u64 t, %1; cvt.u32.u64 %0, t; }"
        : "=r"(a) : "l"(p));
    return a;
}
__device__ __forceinline__ uint32_t f2tf32(float f) {
    uint32_t r;
    asm("cvt.rna.tf32.f32 %0, %1;" : "=r"(r) : "f"(f));
    return r;
}
__device__ __forceinline__ void mma_tf32(float* c, const uint32_t* a, const uint32_t* b) {
    asm volatile(
        "mma.sync.aligned.m16n8k8.row.col.f32.tf32.tf32.f32 "
        "{%0,%1,%2,%3}, {%4,%5,%6,%7}, {%8,%9}, {%0,%1,%2,%3};"
        : "+f"(c[0]), "+f"(c[1]), "+f"(c[2]), "+f"(c[3])
        : "r"(a[0]), "r"(a[1]), "r"(a[2]), "r"(a[3]),
          "r"(b[0]), "r"(b[1]));
}
__device__ __forceinline__ float gelu_exact(float x) {
    return 0.5f * x * (1.0f + erff(x * 0.7071067811865476f));
}

#define CP_ASYNC16(dst, src) \
    asm volatile("cp.async.cg.shared.global [%0], [%1], 16;" :: "r"(dst), "l"(src))
#define CP_COMMIT() asm volatile("cp.async.commit_group;" ::: "memory")
#define CP_WAIT1()  asm volatile("cp.async.wait_group 1;" ::: "memory")

// ---------------------------------------------------------------------------
// Kernel 1: router
// ---------------------------------------------------------------------------
__global__ void router_kernel(const float* __restrict__ x,
                              const float* __restrict__ gw,
                              float* __restrict__ logits_out) {
    int t = blockIdx.x;
    const float* xr = x + (size_t)t * HDIM;

    float acc[NEXP];
#pragma unroll
    for (int e = 0; e < NEXP; e++) acc[e] = 0.f;

    for (int h = threadIdx.x; h < HDIM; h += 256) {
        float xv = xr[h];
        const float4* g = (const float4*)(gw + (size_t)h * NEXP);
        float4 g0 = g[0], g1 = g[1];
        acc[0] += xv * g0.x; acc[1] += xv * g0.y;
        acc[2] += xv * g0.z; acc[3] += xv * g0.w;
        acc[4] += xv * g1.x; acc[5] += xv * g1.y;
        acc[6] += xv * g1.z; acc[7] += xv * g1.w;
    }

    __shared__ float sred[8][NEXP];
    int wid = threadIdx.x >> 5, lane = threadIdx.x & 31;
#pragma unroll
    for (int e = 0; e < NEXP; e++) {
        float v = acc[e];
#pragma unroll
        for (int o = 16; o > 0; o >>= 1) v += __shfl_down_sync(0xffffffffu, v, o);
        if (lane == 0) sred[wid][e] = v;
    }
    __syncthreads();

    if (threadIdx.x == 0) {
        float l[NEXP];
#pragma unroll
        for (int e = 0; e < NEXP; e++) {
            float s = 0.f;
#pragma unroll
            for (int w = 0; w < 8; w++) s += sred[w][e];
            l[e] = s;
            logits_out[(size_t)t * NEXP + e] = s;
        }
        int i0 = 0;
#pragma unroll
        for (int e = 1; e < NEXP; e++) if (l[e] > l[i0]) i0 = e;
        int i1 = -1;
#pragma unroll
        for (int e = 0; e < NEXP; e++) {
            if (e == i0) continue;
            if (i1 < 0 || l[e] > l[i1]) i1 = e;
        }
        float d = expf(l[i1] - l[i0]);
        float inv = 1.0f / (1.0f + d);
        g_sel[t * 2 + 0] = i0;  g_sel[t * 2 + 1] = i1;
        g_wts[t * 2 + 0] = inv; g_wts[t * 2 + 1] = d * inv;
    }
}

// ---------------------------------------------------------------------------
// Kernel 2: deterministic compaction
// ---------------------------------------------------------------------------
__global__ void compact_kernel() {
    int e = threadIdx.x >> 5;
    int lane = threadIdx.x & 31;
    __shared__ int scnt[NEXP], sbase[NEXP];

    int c = 0;
    for (int b = 0; b < T_TOK; b += 32) {
        int t = b + lane;
        bool f = (g_sel[t * 2] == e) || (g_sel[t * 2 + 1] == e);
        unsigned m = __ballot_sync(0xffffffffu, f);
        c += __popc(m);
    }
    if (lane == 0) scnt[e] = c;
    __syncthreads();
    if (threadIdx.x == 0) {
        int s = 0;
        for (int i = 0; i < NEXP; i++) { sbase[i] = s; s += scnt[i]; }
    }
    __syncthreads();
    int base = sbase[e];
    if (lane == 0) { g_cnt[e] = scnt[e]; g_basearr[e] = base; }

    c = 0;
    for (int b = 0; b < T_TOK; b += 32) {
        int t = b + lane;
        int s0 = g_sel[t * 2], s1 = g_sel[t * 2 + 1];
        bool f0 = (s0 == e), f1 = (s1 == e);
        bool f = f0 || f1;
        unsigned m = __ballot_sync(0xffffffffu, f);
        int off = c + __popc(m & ((1u << lane) - 1u));
        if (f) {
            g_tok[base + off] = t;
            g_slot_for[t * 2 + (f0 ? 0 : 1)] = base + off;
        }
        c += __popc(m);
    }
}

// ---------------------------------------------------------------------------
// Kernel 3/4: tf32 mma.sync GEMM
//   block 128(M) x 128(N) x 32(K), 4 warps (each 64x64), 3-stage cp.async.
//   A smem: [128][36] floats  (bank = 4*gid+tig, conflict-free)
//   B smem: [32][132] floats  (bank = 4*tig+gid, conflict-free)
//   smem/CTA = 106KB -> 2 CTAs per SM.
// ---------------------------------------------------------------------------
#define BM 128
#define BN 128
#define BK 32
#define A_ROW_F 36
#define B_ROW_F 132
#define A_BYTES (BM * A_ROW_F * 4)                 // 18432
#define B_OFF   A_BYTES
#define STAGE   (A_BYTES + BK * B_ROW_F * 4)       // 35328
#define NSTAGE  3
#define AROW_OFF (NSTAGE * STAGE)                  // 105984
#define SMEM_SZ (AROW_OFF + BM * 8)                // 107008

template <int KTOT, int NTOT, bool PASSA>
__global__ __launch_bounds__(128, 2) void gemm_cp(const float* __restrict__ Aglob,
                                                  const float* __restrict__ Bglob) {
    constexpr int NT = KTOT / BK;

    extern __shared__ char smem[];
    const int e = blockIdx.z;
    const int cnt = g_cnt[e];
    const int m0 = blockIdx.x * BM;
    if (m0 >= cnt) return;
    const int base = g_basearr[e];
    const int n0 = blockIdx.y * BN;
    const float* Bsrc = Bglob + (size_t)e * KTOT * NTOT;

    const uint32_t sb32 = smem_u32(smem);
    const int tid = threadIdx.x;

    // A-row pointer table in smem (8 rows/thread would burn registers)
    const float** arow = (const float**)(smem + AROW_OFF);
    {
        int r = m0 + tid;
        if (PASSA) {
            int tok = g_tok[base + ((r < cnt) ? r : 0)];
            arow[tid] = Aglob + (size_t)tok * KTOT;
        } else {
            int slot = base + ((r < cnt) ? r : 0);
            arow[tid] = g_hmid + (size_t)slot * KTOT;
        }
    }
    __syncthreads();

    // ---- loader geometry ----
    const int a_m  = tid >> 3;          // + i*16, i<8
    const int a_c8 = tid & 7;           // 16B chunk in 128B k-row
    const int b_k  = tid >> 5;          // + i*4, i<8
    const int b_c  = tid & 31;          // 16B chunk in 512B n-row

    auto issue = [&](int kt, int s) {
        uint32_t so = sb32 + s * STAGE;
        const int k0 = kt * BK;
#pragma unroll
        for (int i = 0; i < 8; i++) {
            int m = a_m + i * 16;
            CP_ASYNC16(so + (uint32_t)(m * (A_ROW_F * 4) + a_c8 * 16),
                       arow[m] + k0 + a_c8 * 4);
        }
        const float* bbase = Bsrc + (size_t)k0 * NTOT + n0 + b_c * 4;
#pragma unroll
        for (int i = 0; i < 8; i++) {
            int k = b_k + i * 4;
            CP_ASYNC16(so + (uint32_t)(B_OFF + k * (B_ROW_F * 4) + b_c * 16),
                       bbase + (size_t)k * NTOT);
        }
    };

    issue(0, 0); CP_COMMIT();
    issue(1, 1); CP_COMMIT();

    const int wid = tid >> 5, lane = tid & 31;
    const int wm = (wid & 1) * 64;
    const int wn = (wid >> 1) * 64;
    const int gid = lane >> 2, tig = lane & 3;

    float acc[4][8][4];
#pragma unroll
    for (int i = 0; i < 4; i++)
#pragma unroll
        for (int j = 0; j < 8; j++)
#pragma unroll
            for (int k = 0; k < 4; k++) acc[i][j][k] = 0.f;

#pragma unroll 1
    for (int kt = 0; kt < NT; kt++) {
        CP_WAIT1();              // stage kt resident
        __syncthreads();         // stage kt-1 reads complete; loads visible
        if (kt + 2 < NT) issue(kt + 2, (kt + 2) % NSTAGE);
        CP_COMMIT();

        const int s = kt % NSTAGE;
        const float* As = (const float*)(smem + s * STAGE);
        const float* Bs = (const float*)(smem + s * STAGE + B_OFF);

#pragma unroll
        for (int ks = 0; ks < 4; ks++) {
            const int kb = ks * 8;
            uint32_t af[4][4], bf[8][2];
#pragma unroll
            for (int ms = 0; ms < 4; ms++) {
                int am = wm + ms * 16 + gid;
                af[ms][0] = f2tf32(As[am * A_ROW_F + kb + tig]);
                af[ms][1] = f2tf32(As[(am + 8) * A_ROW_F + kb + tig]);
                af[ms][2] = f2tf32(As[am * A_ROW_F + kb + tig + 4]);
                af[ms][3] = f2tf32(As[(am + 8) * A_ROW_F + kb + tig + 4]);
            }
#pragma unroll
            for (int ns = 0; ns < 8; ns++) {
                int bn = wn + ns * 8 + gid;
                bf[ns][0] = f2tf32(Bs[(kb + tig) * B_ROW_F + bn]);
                bf[ns][1] = f2tf32(Bs[(kb + tig + 4) * B_ROW_F + bn]);
            }
#pragma unroll
            for (int ms = 0; ms < 4; ms++)
#pragma unroll
                for (int ns = 0; ns < 8; ns++)
                    mma_tf32(acc[ms][ns], af[ms], bf[ns]);
        }
    }

    // ---- epilogue: registers -> gmem ----
    float* Cg = PASSA ? g_hmid : g_y;
#pragma unroll
    for (int ms = 0; ms < 4; ms++) {
        int r0 = wm + ms * 16 + gid;
        int r1 = r0 + 8;
        bool ok0 = (m0 + r0) < cnt;
        bool ok1 = (m0 + r1) < cnt;
        size_t row0 = (size_t)(base + m0 + r0) * NTOT + n0;
        size_t row1 = (size_t)(base + m0 + r1) * NTOT + n0;
#pragma unroll
        for (int ns = 0; ns < 8; ns++) {
            int c = wn + ns * 8 + tig * 2;
            float v0 = acc[ms][ns][0], v1 = acc[ms][ns][1];
            float v2 = acc[ms][ns][2], v3 = acc[ms][ns][3];
            if (PASSA) {
                v0 = gelu_exact(v0); v1 = gelu_exact(v1);
                v2 = gelu_exact(v2); v3 = gelu_exact(v3);
            }
            if (ok0) *(float2*)(Cg + row0 + c) = make_float2(v0, v1);
            if (ok1) *(float2*)(Cg + row1 + c) = make_float2(v2, v3);
        }
    }
}

// ---------------------------------------------------------------------------
// Kernel 5: combine
// ---------------------------------------------------------------------------
__global__ void combine_kernel(const float* __restrict__ bias,
                               float* __restrict__ out) {
    int gid = blockIdx.x * 256 + threadIdx.x;
    if (gid >= T_TOK * (HDIM / 4)) return;
    int t = gid >> 9;
    int h4 = gid & 511;
    int s0 = g_slot_for[t * 2], s1 = g_slot_for[t * 2 + 1];
    float w0 = g_wts[t * 2], w1 = g_wts[t * 2 + 1];
    float4 y0 = *(const float4*)(g_y + (size_t)s0 * HDIM + h4 * 4);
    float4 y1 = *(const float4*)(g_y + (size_t)s1 * HDIM + h4 * 4);
    float4 b = *(const float4*)(bias + h4 * 4);
    float4 o;
    o.x = b.x + w0 * y0.x + w1 * y1.x;
    o.y = b.y + w0 * y0.y + w1 * y1.y;
    o.z = b.z + w0 * y0.z + w1 * y1.z;
    o.w = b.w + w0 * y0.w + w1 * y1.w;
    *(float4*)(out + (size_t)t * HDIM + h4 * 4) = o;
}

// ---------------------------------------------------------------------------
// launch
// ---------------------------------------------------------------------------
extern "C" void kernel_launch(void* const* d_in, const int* in_sizes, int n_in,
                              void* d_out, int out_size) {
    const float* x     = (const float*)d_in[0];   // [2,2048,2048]
    const float* gw    = (const float*)d_in[1];   // [2048,8]
    const float* w_in  = (const float*)d_in[2];   // [8,2048,8192]
    const float* w_out = (const float*)d_in[3];   // [8,8192,2048]
    const float* bias  = (const float*)d_in[4];   // [2048]
    (void)in_sizes; (void)n_in; (void)out_size;

    float* out    = (float*)d_out;
    float* logits = out + (size_t)T_TOK * HDIM;

    cudaFuncSetAttribute(gemm_cp<HDIM, IDIM, true>,
                         cudaFuncAttributeMaxDynamicSharedMemorySize, SMEM_SZ);
    cudaFuncSetAttribute(gemm_cp<IDIM, HDIM, false>,
                         cudaFuncAttributeMaxDynamicSharedMemorySize, SMEM_SZ);

    router_kernel<<<T_TOK, 256>>>(x, gw, logits);
    compact_kernel<<<1, 256>>>();

    dim3 ga(T_TOK / BM, IDIM / BN, NEXP);         // (32, 64, 8)
    gemm_cp<HDIM, IDIM, true><<<ga, 128, SMEM_SZ>>>(x, w_in);

    dim3 gb(T_TOK / BM, HDIM / BN, NEXP);         // (32, 16, 8)
    gemm_cp<IDIM, HDIM, false><<<gb, 128, SMEM_SZ>>>(nullptr, w_out);

    combine_kernel<<<(T_TOK * (HDIM / 4) + 255) / 256, 256>>>(bias, out);
}